// round 17
// baseline (speedup 1.0000x reference)
#include <cuda_runtime.h>
#include <math.h>

#define NPTS    16384               // 8 * 2048 points per cloud
#define DIM     32
#define DIM2    (DIM * DIM)
#define NCELLS  (DIM * DIM * DIM)   // 32768
#define TOTC    (2 * NCELLS)        // 65536 (flattened, both clouds)
#define ORG     (-5.0f)
#define H       0.3125f
#define INVH    3.2f
#define GRID    512                 // 4 blocks/SM cap -> single co-resident wave
#define TPB     256

// INVARIANT: g_count all-zero on entry (zero-init at load; re-zeroed in P2).
__device__ float4   g_sorted[2 * NPTS];     // flat, cell-grouped (order arbitrary)
__device__ int      g_count [TOTC];
__device__ int2     g_span  [TOTC];         // per-cell [start, end)
__device__ int      g_cursor[TOTC];
__device__ int      g_cellid[2 * NPTS];
__device__ int      g_qstart[2 * NPTS];     // query's own sorted position base? (unused)
__device__ int      g_pending[2 * NPTS];
__device__ int      g_pcount;
__device__ int      g_alloc;
__device__ unsigned g_barcnt;
__device__ unsigned g_bargen;               // monotonic across replays

__device__ __forceinline__ int cell_coord(float v) {
    int c = (int)floorf((v - ORG) * INVH);
    return min(DIM - 1, max(0, c));
}

__device__ __forceinline__ void grid_barrier() {
    __syncthreads();
    if (threadIdx.x == 0) {
        volatile unsigned* genp = &g_bargen;
        unsigned g = *genp;
        __threadfence();
        if (atomicAdd(&g_barcnt, 1u) == (unsigned)(gridDim.x - 1)) {
            g_barcnt = 0;
            __threadfence();
            atomicAdd(&g_bargen, 1u);       // release
        } else {
            while (*genp == g) __nanosleep(32);
        }
        __threadfence();                    // acquire
    }
    __syncthreads();
}

// Scan one cell's span (int2 = [start, end)); points split stride-4 over quad.
__device__ __forceinline__ void scan_q4(const float4* __restrict__ tgt,
                                        const int2* __restrict__ spn,
                                        int cell, int sub,
                                        float qx, float qy, float qz,
                                        float& best2) {
    const int2 se = spn[cell];              // single LDG.64
    for (int p = se.x + sub; p < se.y; p += 4) {
        const float4 b = tgt[p];
        const float dx = qx - b.x;
        const float dy = qy - b.y;
        const float dz = qz - b.z;
        const float d2 = fmaf(dx, dx, fmaf(dy, dy, dz * dz));
        best2 = fminf(best2, d2);
    }
}

__global__ void __launch_bounds__(TPB, 4)
fused_kernel(const float* __restrict__ pc1,
             const float* __restrict__ pc2,
             float* __restrict__ out) {
    const int tid  = blockIdx.x * blockDim.x + threadIdx.x;   // 0 .. 131071
    const int lane = threadIdx.x & 31;
    const int wid  = threadIdx.x >> 5;

    // ---------------- P0: init
    if (tid == 0) { out[0] = 0.0f; g_pcount = 0; g_alloc = 0; }

    // ---------------- P1: histogram (1 point per thread, tid < 32768)
    if (tid < 2 * NPTS) {
        int c = (tid >= NPTS) ? 1 : 0;
        int j = tid - c * NPTS;
        const float* pc = c ? pc2 : pc1;
        float x = pc[3 * j + 0], y = pc[3 * j + 1], z = pc[3 * j + 2];
        int cell = c * NCELLS
                 + (cell_coord(z) * DIM + cell_coord(y)) * DIM + cell_coord(x);
        g_cellid[tid] = cell;
        atomicAdd(&g_count[cell], 1);
    }
    grid_barrier();

    // ---------------- P2: bump allocation (replaces the prefix scan).
    // One thread per cell; only occupied cells touch the global counter.
    if (tid < TOTC) {
        const int cnt = g_count[tid];
        int s = 0;
        if (cnt) {
            s = atomicAdd(&g_alloc, cnt);
            g_count[tid] = 0;               // restore all-zero invariant
        }
        g_span  [tid] = make_int2(s, s + cnt);
        g_cursor[tid] = s;
    }
    grid_barrier();

    // ---------------- P3: scatter into cell-grouped order
    if (tid < 2 * NPTS) {
        int c = (tid >= NPTS) ? 1 : 0;
        int j = tid - c * NPTS;
        const float* pc = c ? pc2 : pc1;
        float x = pc[3 * j + 0], y = pc[3 * j + 1], z = pc[3 * j + 2];
        int pos = atomicAdd(&g_cursor[g_cellid[tid]], 1);
        g_sorted[pos] = make_float4(x, y, z, 0.0f);
    }
    grid_barrier();

    // ---------------- P4: box(1) quad-cooperative query w/ slab culling
    float dsum = 0.0f;
    {
        const int sub = threadIdx.x & 3;
        const unsigned qmask = 0xFu << (threadIdx.x & 28);
        const int gq  = tid >> 2;             // exactly one quad per query
        const int dir = gq >> 14;
        const int qi  = gq & (NPTS - 1);
        const int tc  = dir ^ 1;

        // Query point from the ORIGINAL input (no dependence on sort order).
        const float* pcq = dir ? pc2 : pc1;
        const float qx = pcq[3 * qi + 0];
        const float qy = pcq[3 * qi + 1];
        const float qz = pcq[3 * qi + 2];

        const int cx = cell_coord(qx);
        const int cy = cell_coord(qy);
        const int cz = cell_coord(qz);
        const float fx = qx - (ORG + (float)cx * H);
        const float fy = qy - (ORG + (float)cy * H);
        const float fz = qz - (ORG + (float)cz * H);
        const float mfr = fmaxf(0.0f,
            fminf(fminf(fminf(fx, H - fx), fminf(fy, H - fy)),
                  fminf(fz, H - fz)));

        const float4* __restrict__ tgt = g_sorted;
        const int2*   __restrict__ spn = g_span + tc * NCELLS;

        float best2 = 3.0e38f;

        const int cc = (cz * DIM + cy) * DIM + cx;
        scan_q4(tgt, spn, cc, sub, qx, qy, qz, best2);
        best2 = fminf(best2, __shfl_xor_sync(qmask, best2, 1));
        best2 = fminf(best2, __shfl_xor_sync(qmask, best2, 2));

        {
            const float gate = best2;
            const float sx2[3] = { fx * fx, 0.0f, (H - fx) * (H - fx) };
            const float sy2[3] = { fy * fy, 0.0f, (H - fy) * (H - fy) };
            const float sz2[3] = { fz * fz, 0.0f, (H - fz) * (H - fz) };
            const bool okx[3] = { cx > 0, true, cx < DIM - 1 };
            const bool oky[3] = { cy > 0, true, cy < DIM - 1 };
            const bool okz[3] = { cz > 0, true, cz < DIM - 1 };

            #pragma unroll
            for (int iz = 0; iz < 3; ++iz) {
                if (!okz[iz]) continue;
                const float rz = sz2[iz];
                if (rz >= gate) continue;
                #pragma unroll
                for (int iy = 0; iy < 3; ++iy) {
                    if (!oky[iy]) continue;
                    const float rzy = rz + sy2[iy];
                    if (rzy >= gate) continue;
                    const int rb = (cz + iz - 1) * DIM2 + (cy + iy - 1) * DIM + cx;
                    #pragma unroll
                    for (int ix = 0; ix < 3; ++ix) {
                        if (iz == 1 && iy == 1 && ix == 1) continue;
                        if (!okx[ix]) continue;
                        if (rzy + sx2[ix] >= gate) continue;
                        scan_q4(tgt, spn, rb + ix - 1, sub, qx, qy, qz, best2);
                    }
                }
            }
            best2 = fminf(best2, __shfl_xor_sync(qmask, best2, 1));
            best2 = fminf(best2, __shfl_xor_sync(qmask, best2, 2));
        }

        const float bound = H + mfr;
        if (sub == 0) {
            if (best2 <= bound * bound) {
                dsum += sqrtf(fmaxf(best2, 0.0f));
            } else {
                int idx = atomicAdd(&g_pcount, 1);
                g_pending[idx] = gq;
            }
        }
    }
    grid_barrier();

    // ---------------- P5: warp-per-query brute force for pending
    {
        const int gwarp = tid >> 5;
        const int nwarp = (GRID * TPB) >> 5;              // 4096
        const int n = g_pcount;
        const float4* __restrict__ all = g_sorted;
        for (int w = gwarp; w < n; w += nwarp) {
            const int gq  = g_pending[w];
            const int dir = gq >> 14;
            const int qi  = gq & (NPTS - 1);
            const float* pcq = dir ? pc2 : pc1;
            const float qx = pcq[3 * qi + 0];
            const float qy = pcq[3 * qi + 1];
            const float qz = pcq[3 * qi + 2];
            // Targets of the opposite cloud occupy a contiguous half of
            // g_sorted? No — allocation interleaves clouds. Scan the raw
            // input instead (coalesced, L2-resident).
            const float* pct = dir ? pc1 : pc2;

            float best2 = 3.0e38f;
            for (int p = lane; p < NPTS; p += 32) {
                const float dx = qx - pct[3 * p + 0];
                const float dy = qy - pct[3 * p + 1];
                const float dz = qz - pct[3 * p + 2];
                const float d2 = fmaf(dx, dx, fmaf(dy, dy, dz * dz));
                best2 = fminf(best2, d2);
            }
            #pragma unroll
            for (int off = 16; off > 0; off >>= 1)
                best2 = fminf(best2, __shfl_xor_sync(0xFFFFFFFFu, best2, off));
            if (lane == 0) dsum += sqrtf(fmaxf(best2, 0.0f));
            (void)all;
        }
    }

    // ---------------- Final: block reduction, one atomicAdd per block.
    __shared__ float warp_sums[TPB / 32];
    float v = dsum;
    #pragma unroll
    for (int off = 16; off > 0; off >>= 1)
        v += __shfl_xor_sync(0xFFFFFFFFu, v, off);
    if (lane == 0) warp_sums[wid] = v;
    __syncthreads();
    if (threadIdx.x < 32) {
        float s = (lane < TPB / 32) ? warp_sums[lane] : 0.0f;
        #pragma unroll
        for (int off = (TPB / 64); off > 0; off >>= 1)
            s += __shfl_xor_sync(0xFFFFFFFFu, s, off);
        if (lane == 0 && s != 0.0f)
            atomicAdd(out, s * (1.0f / (float)NPTS));
    }
}

extern "C" void kernel_launch(void* const* d_in, const int* in_sizes, int n_in,
                              void* d_out, int out_size) {
    const float* pc1 = (const float*)d_in[0];
    const float* pc2 = (const float*)d_in[1];
    float* out = (float*)d_out;

    fused_kernel<<<GRID, TPB>>>(pc1, pc2, out);
}